// round 13
// baseline (speedup 1.0000x reference)
#include <cuda_runtime.h>
#include <cuda_fp16.h>
#include <stdint.h>

#define B_   4
#define T_   256
#define U_   128
#define DE   512
#define DP   640
#define JD   1024
#define VO   1025

#define KC     64
#define NCHUNK 16

// ---- dynamic smem (joint): epilogue staging only ----
#define SM_TOTAL (128*132*4)             // 67584 -> 2 CTAs/SM

// ---- device scratch ----
__device__ __align__(16) float g_enc_proj[B_*T_*JD];      // 4 MB
__device__ __align__(16) float g_pred_proj[B_*U_*JD];     // 2 MB
// W fragments: uint2 [c(16)][n8(128)][kh(4)][lane(32)]   // 2 MB
__device__ __align__(16) uint2 g_Wfrag[NCHUNK*128*4*32];
// A fragments: uint4 [bt(1024)][c(16)][mh(8)][kh(4)][lane(32)]  // 256 MB
__device__ __align__(16) uint4 g_Afrag[(size_t)B_*T_*NCHUNK*8*4*32];

// =====================================================================
// helpers
// =====================================================================
__device__ __forceinline__ void mma16816(float* c, const uint32_t* a, const uint32_t* b) {
    asm volatile(
        "mma.sync.aligned.m16n8k16.row.col.f32.f16.f16.f32 "
        "{%0,%1,%2,%3},{%4,%5,%6,%7},{%8,%9},{%0,%1,%2,%3};"
        : "+f"(c[0]), "+f"(c[1]), "+f"(c[2]), "+f"(c[3])
        : "r"(a[0]), "r"(a[1]), "r"(a[2]), "r"(a[3]), "r"(b[0]), "r"(b[1]));
}

// =====================================================================
// kernel 1: BOTH fp32 projection GEMMs in one launch (z selects problem)
// z=0: enc [1024,512]@[512,1024] ; z=1: pred [512,640]@[640,1024]
// =====================================================================
__global__ void __launch_bounds__(256) proj_both(
    const float* __restrict__ A0, const float* __restrict__ W0,
    const float* __restrict__ bias0, float* __restrict__ C0,
    const float* __restrict__ A1, const float* __restrict__ W1,
    const float* __restrict__ bias1, float* __restrict__ C1)
{
    const int which = blockIdx.z;
    const float* A    = which ? A1 : A0;
    const float* W    = which ? W1 : W0;
    const float* bias = which ? bias1 : bias0;
    float* C          = which ? C1 : C0;
    const int M = which ? (B_ * U_) : (B_ * T_);
    const int K = which ? DP : DE;
    const int J = JD;

    const int m0 = blockIdx.y * 64;
    if (m0 >= M) return;
    const int n0 = blockIdx.x * 64;

    __shared__ float As[16][68];
    __shared__ float Bs[16][64];
    const int tx = threadIdx.x & 15;
    const int ty = threadIdx.x >> 4;

    float acc[4][4] = {};

    for (int k0 = 0; k0 < K; k0 += 16) {
        {
            int t = threadIdx.x;
            int m  = t >> 2, k4 = (t & 3) * 4;
            float4 a = *(const float4*)(A + (size_t)(m0 + m) * K + k0 + k4);
            As[k4 + 0][m] = a.x; As[k4 + 1][m] = a.y;
            As[k4 + 2][m] = a.z; As[k4 + 3][m] = a.w;
            int kk = t >> 4, n4 = (t & 15) * 4;
            *(float4*)&Bs[kk][n4] = *(const float4*)(W + (size_t)(k0 + kk) * J + n0 + n4);
        }
        __syncthreads();
        #pragma unroll
        for (int k = 0; k < 16; k++) {
            float a[4], b[4];
            *(float4*)a = *(float4*)&As[k][ty * 4];
            *(float4*)b = *(float4*)&Bs[k][tx * 4];
            #pragma unroll
            for (int i = 0; i < 4; i++)
                #pragma unroll
                for (int j = 0; j < 4; j++)
                    acc[i][j] += a[i] * b[j];
        }
        __syncthreads();
    }
    #pragma unroll
    for (int i = 0; i < 4; i++) {
        int m = m0 + ty * 4 + i;
        #pragma unroll
        for (int j = 0; j < 4; j++) {
            int n = n0 + tx * 4 + j;
            C[(size_t)m * J + n] = acc[i][j] + bias[n];
        }
    }
}

// =====================================================================
// kernel 2: W_out[:, 0:1024] -> fp16 B-fragments (col-major n8k16)
// =====================================================================
__global__ void __launch_bounds__(256) prep_w(const float* __restrict__ W) {
    int idx = blockIdx.x * 256 + threadIdx.x;     // 0..262143
    int lane = idx & 31;
    int kh   = (idx >> 5) & 3;
    int n8   = (idx >> 7) & 127;
    int c    = idx >> 14;
    int j = c * 64 + kh * 16 + (lane & 3) * 2;
    int n = n8 * 8 + (lane >> 2);
    __half2 b0 = __floats2half2_rn(W[(size_t)j * VO + n], W[(size_t)(j + 1) * VO + n]);
    __half2 b1 = __floats2half2_rn(W[(size_t)(j + 8) * VO + n], W[(size_t)(j + 9) * VO + n]);
    g_Wfrag[idx] = make_uint2(*(uint32_t*)&b0, *(uint32_t*)&b1);
}

// =====================================================================
// kernel 3: precompute A-fragments + blank column (v2: coalesced + smem
// transpose). Stage 1: coalesced pred read -> relu -> fp16 tile in smem.
// Stage 2: re-read in frag order -> coalesced STG of uint4 fragments.
// =====================================================================
#define HP 72   // fp16 tile pitch (halves); 144B -> conflict-free patterns
__global__ void __launch_bounds__(256) precompute_A(
    const float* __restrict__ Wout, const float* __restrict__ bout,
    float* __restrict__ out)
{
    __shared__ float enc_s[JD];
    __shared__ float wb_s[JD];
    __shared__ __half hbuf[128 * HP];    // 18432 B
    const int bt   = blockIdx.x;
    const int b    = bt >> 8;
    const int t    = threadIdx.x;
    const int warp = t >> 5;
    const int lane = t & 31;

    ((float4*)enc_s)[t] = ((const float4*)(g_enc_proj + (size_t)bt * JD))[t];
    for (int i = t; i < JD; i += 256)
        wb_s[i] = Wout[(size_t)i * VO + (VO - 1)];
    __syncthreads();

    // stage-1 mapping: row u = t>>1, half h = t&1 (32 cols)
    const int u = t >> 1, h = t & 1;
    const float* prow = g_pred_proj + ((size_t)(b * U_ + u)) * JD + h * 32;
    // stage-2 mapping: frag (r, cl)
    const int r  = warp * 16 + (lane >> 2);
    const int cl = (lane & 3) * 2;
    float accb = 0.f;

    for (int c = 0; c < NCHUNK; c++) {
        // ---- stage 1: coalesced read + relu + fp16 -> hbuf ----
        {
            const int j0 = c * KC + h * 32;
            const float4* p4 = (const float4*)(prow + c * KC);
            __half* dst = hbuf + u * HP + h * 32;
            #pragma unroll
            for (int q = 0; q < 4; q++) {
                float4 pa = p4[2 * q], pb = p4[2 * q + 1];
                float h0 = fmaxf(pa.x + enc_s[j0 + q * 8 + 0], 0.f);
                float h1 = fmaxf(pa.y + enc_s[j0 + q * 8 + 1], 0.f);
                float h2 = fmaxf(pa.z + enc_s[j0 + q * 8 + 2], 0.f);
                float h3 = fmaxf(pa.w + enc_s[j0 + q * 8 + 3], 0.f);
                float h4 = fmaxf(pb.x + enc_s[j0 + q * 8 + 4], 0.f);
                float h5 = fmaxf(pb.y + enc_s[j0 + q * 8 + 5], 0.f);
                float h6 = fmaxf(pb.z + enc_s[j0 + q * 8 + 6], 0.f);
                float h7 = fmaxf(pb.w + enc_s[j0 + q * 8 + 7], 0.f);
                accb += h0 * wb_s[j0 + q * 8 + 0] + h1 * wb_s[j0 + q * 8 + 1]
                      + h2 * wb_s[j0 + q * 8 + 2] + h3 * wb_s[j0 + q * 8 + 3]
                      + h4 * wb_s[j0 + q * 8 + 4] + h5 * wb_s[j0 + q * 8 + 5]
                      + h6 * wb_s[j0 + q * 8 + 6] + h7 * wb_s[j0 + q * 8 + 7];
                __half2 v0 = __floats2half2_rn(h0, h1);
                __half2 v1 = __floats2half2_rn(h2, h3);
                __half2 v2 = __floats2half2_rn(h4, h5);
                __half2 v3 = __floats2half2_rn(h6, h7);
                *(uint4*)(dst + q * 8) = make_uint4(
                    *(uint32_t*)&v0, *(uint32_t*)&v1, *(uint32_t*)&v2, *(uint32_t*)&v3);
            }
        }
        __syncthreads();

        // ---- stage 2: frag-order gather from hbuf -> coalesced STG ----
        {
            uint4* aOut = g_Afrag + (((size_t)bt * NCHUNK + c) * 8 + warp) * 128 + lane;
            #pragma unroll
            for (int kh = 0; kh < 4; kh++) {
                const int jc = kh * 16 + cl;
                uint32_t a0 = *(const uint32_t*)&hbuf[r * HP + jc];
                uint32_t a1 = *(const uint32_t*)&hbuf[(r + 8) * HP + jc];
                uint32_t a2 = *(const uint32_t*)&hbuf[r * HP + jc + 8];
                uint32_t a3 = *(const uint32_t*)&hbuf[(r + 8) * HP + jc + 8];
                aOut[kh * 32] = make_uint4(a0, a1, a2, a3);
            }
        }
        __syncthreads();
    }

    // blank column: threads (2u, 2u+1) are adjacent lanes
    accb += __shfl_xor_sync(0xffffffffu, accb, 1);
    if (h == 0)
        out[((size_t)bt * U_ + u) * VO + (VO - 1)] = accb + bout[VO - 1];
}

// =====================================================================
// kernel 4: joint GEMM — direct-LDG fragments (round-11 proven loop)
// CTA 128x128 (bt x n-tile), warps 2(M)x4(N), warp tile 64x32
// =====================================================================
__global__ void __launch_bounds__(256, 2) joint_main(
    const float* __restrict__ bout, float* __restrict__ out)
{
    extern __shared__ char sm[];

    const int bt    = blockIdx.y;          // 0..1023
    const int ntile = blockIdx.x;          // 0..7
    const int n0    = ntile * 128;
    const int t     = threadIdx.x;
    const int warp  = t >> 5;
    const int lane  = t & 31;
    const int wm    = warp >> 2;           // 0..1 (M)
    const int wn    = warp & 3;            // 0..3 (N)

    float acc[4][4][4] = {};

    const uint4* aC = g_Afrag + (((size_t)bt * NCHUNK * 8) + wm * 4) * 128 + lane;
    const uint2* bC = g_Wfrag + (size_t)(ntile * 16 + wn * 4) * 128 + lane;

    for (int c = 0; c < NCHUNK; c++) {
        #pragma unroll
        for (int kh = 0; kh < 4; kh++) {
            uint2 bq[4];
            #pragma unroll
            for (int nt = 0; nt < 4; nt++)
                bq[nt] = bC[(size_t)c * 16384 + nt * 128 + kh * 32];
            #pragma unroll
            for (int mt = 0; mt < 4; mt++) {
                uint4 av = aC[(size_t)c * 1024 + mt * 128 + kh * 32];
                uint32_t a[4] = {av.x, av.y, av.z, av.w};
                #pragma unroll
                for (int nt = 0; nt < 4; nt++)
                    mma16816(acc[mt][nt], a, (const uint32_t*)&bq[nt]);
            }
        }
    }

    // ---- coalesced epilogue: stage f32 tile in smem, then contiguous STG ----
    float* stg = (float*)sm;               // 128 x 132 floats = 67584 B
    const int gid = lane >> 2, tig = lane & 3;
    #pragma unroll
    for (int mt = 0; mt < 4; mt++) {
        #pragma unroll
        for (int nt = 0; nt < 4; nt++) {
            float* cv = acc[mt][nt];
            int u0 = wm * 64 + mt * 16 + gid;
            int c0 = wn * 32 + nt * 8 + tig * 2;
            *(float2*)&stg[u0 * 132 + c0]       = make_float2(cv[0], cv[1]);
            *(float2*)&stg[(u0 + 8) * 132 + c0] = make_float2(cv[2], cv[3]);
        }
    }
    __syncthreads();

    float bo[4];
    #pragma unroll
    for (int i = 0; i < 4; i++) bo[i] = bout[n0 + i * 32 + lane];

    #pragma unroll
    for (int ri = 0; ri < 16; ri++) {
        int row = warp * 16 + ri;
        float* orow = out + ((size_t)bt * U_ + row) * VO + n0;
        #pragma unroll
        for (int i = 0; i < 4; i++)
            orow[i * 32 + lane] = stg[row * 132 + i * 32 + lane] + bo[i];
    }
}

// =====================================================================
extern "C" void kernel_launch(void* const* d_in, const int* in_sizes, int n_in,
                              void* d_out, int out_size)
{
    (void)in_sizes; (void)n_in; (void)out_size;
    const float* enc    = (const float*)d_in[0];
    const float* pred   = (const float*)d_in[1];
    const float* W_enc  = (const float*)d_in[2];
    const float* b_enc  = (const float*)d_in[3];
    const float* W_pred = (const float*)d_in[4];
    const float* b_pred = (const float*)d_in[5];
    const float* W_out  = (const float*)d_in[6];
    const float* b_out  = (const float*)d_in[7];
    float* out = (float*)d_out;

    void *pe, *pp;
    cudaGetSymbolAddress(&pe, g_enc_proj);
    cudaGetSymbolAddress(&pp, g_pred_proj);
    float* genc  = (float*)pe;
    float* gpred = (float*)pp;

    cudaFuncSetAttribute(joint_main, cudaFuncAttributeMaxDynamicSharedMemorySize, SM_TOTAL);

    dim3 pg(JD / 64, (B_ * T_) / 64, 2);     // z=0 enc, z=1 pred (y-guard)
    proj_both<<<pg, 256>>>(enc, W_enc, b_enc, genc,
                           pred, W_pred, b_pred, gpred);
    prep_w<<<1024, 256>>>(W_out);
    precompute_A<<<B_ * T_, 256>>>(W_out, b_out, out);

    dim3 grid(8, B_ * T_);               // 8 n-tiles x 1024 (b,t) tiles
    joint_main<<<grid, 256, SM_TOTAL>>>(b_out, out);
}

// round 14
// speedup vs baseline: 1.1549x; 1.1549x over previous
#include <cuda_runtime.h>
#include <cuda_fp16.h>
#include <stdint.h>

#define B_   4
#define T_   256
#define U_   128
#define DE   512
#define DP   640
#define JD   1024
#define VO   1025

#define KC     64
#define NCHUNK 16

// ---- dynamic smem (joint): epilogue staging only ----
#define SM_TOTAL (128*132*4)             // 67584 -> 2 CTAs/SM

// ---- device scratch ----
__device__ __align__(16) float g_enc_proj[B_*T_*JD];      // 4 MB
__device__ __align__(16) float g_pred_proj[B_*U_*JD];     // 2 MB
// W fragments: uint2 [c(16)][n8(128)][kh(4)][lane(32)]   // 2 MB
__device__ __align__(16) uint2 g_Wfrag[NCHUNK*128*4*32];
// A fragments: uint4 [bt(1024)][c(16)][mh(8)][kh(4)][lane(32)]  // 256 MB
__device__ __align__(16) uint4 g_Afrag[(size_t)B_*T_*NCHUNK*8*4*32];

// =====================================================================
// helpers
// =====================================================================
__device__ __forceinline__ void mma16816(float* c, const uint32_t* a, const uint32_t* b) {
    asm volatile(
        "mma.sync.aligned.m16n8k16.row.col.f32.f16.f16.f32 "
        "{%0,%1,%2,%3},{%4,%5,%6,%7},{%8,%9},{%0,%1,%2,%3};"
        : "+f"(c[0]), "+f"(c[1]), "+f"(c[2]), "+f"(c[3])
        : "r"(a[0]), "r"(a[1]), "r"(a[2]), "r"(a[3]), "r"(b[0]), "r"(b[1]));
}

// =====================================================================
// kernel 1: BOTH fp32 projection GEMMs in one launch (z selects problem)
// =====================================================================
__global__ void __launch_bounds__(256) proj_both(
    const float* __restrict__ A0, const float* __restrict__ W0,
    const float* __restrict__ bias0, float* __restrict__ C0,
    const float* __restrict__ A1, const float* __restrict__ W1,
    const float* __restrict__ bias1, float* __restrict__ C1)
{
    const int which = blockIdx.z;
    const float* A    = which ? A1 : A0;
    const float* W    = which ? W1 : W0;
    const float* bias = which ? bias1 : bias0;
    float* C          = which ? C1 : C0;
    const int M = which ? (B_ * U_) : (B_ * T_);
    const int K = which ? DP : DE;
    const int J = JD;

    const int m0 = blockIdx.y * 64;
    if (m0 >= M) return;
    const int n0 = blockIdx.x * 64;

    __shared__ float As[16][68];
    __shared__ float Bs[16][64];
    const int tx = threadIdx.x & 15;
    const int ty = threadIdx.x >> 4;

    float acc[4][4] = {};

    for (int k0 = 0; k0 < K; k0 += 16) {
        {
            int t = threadIdx.x;
            int m  = t >> 2, k4 = (t & 3) * 4;
            float4 a = *(const float4*)(A + (size_t)(m0 + m) * K + k0 + k4);
            As[k4 + 0][m] = a.x; As[k4 + 1][m] = a.y;
            As[k4 + 2][m] = a.z; As[k4 + 3][m] = a.w;
            int kk = t >> 4, n4 = (t & 15) * 4;
            *(float4*)&Bs[kk][n4] = *(const float4*)(W + (size_t)(k0 + kk) * J + n0 + n4);
        }
        __syncthreads();
        #pragma unroll
        for (int k = 0; k < 16; k++) {
            float a[4], b[4];
            *(float4*)a = *(float4*)&As[k][ty * 4];
            *(float4*)b = *(float4*)&Bs[k][tx * 4];
            #pragma unroll
            for (int i = 0; i < 4; i++)
                #pragma unroll
                for (int j = 0; j < 4; j++)
                    acc[i][j] += a[i] * b[j];
        }
        __syncthreads();
    }
    #pragma unroll
    for (int i = 0; i < 4; i++) {
        int m = m0 + ty * 4 + i;
        #pragma unroll
        for (int j = 0; j < 4; j++) {
            int n = n0 + tx * 4 + j;
            C[(size_t)m * J + n] = acc[i][j] + bias[n];
        }
    }
}

// =====================================================================
// kernel 2: W_out[:, 0:1024] -> fp16 B-fragments (col-major n8k16)
// =====================================================================
__global__ void __launch_bounds__(256) prep_w(const float* __restrict__ W) {
    int idx = blockIdx.x * 256 + threadIdx.x;     // 0..262143
    int lane = idx & 31;
    int kh   = (idx >> 5) & 3;
    int n8   = (idx >> 7) & 127;
    int c    = idx >> 14;
    int j = c * 64 + kh * 16 + (lane & 3) * 2;
    int n = n8 * 8 + (lane >> 2);
    __half2 b0 = __floats2half2_rn(W[(size_t)j * VO + n], W[(size_t)(j + 1) * VO + n]);
    __half2 b1 = __floats2half2_rn(W[(size_t)(j + 8) * VO + n], W[(size_t)(j + 9) * VO + n]);
    g_Wfrag[idx] = make_uint2(*(uint32_t*)&b0, *(uint32_t*)&b1);
}

// =====================================================================
// kernel 3: precompute fp16 joint activations as A-fragments + blank col
// (round-11 proven version)
// =====================================================================
__global__ void __launch_bounds__(256) precompute_A(
    const float* __restrict__ Wout, const float* __restrict__ bout,
    float* __restrict__ out)
{
    __shared__ float enc_s[JD];
    __shared__ float wb_s[JD];
    const int bt   = blockIdx.x;
    const int b    = bt >> 8;
    const int t    = threadIdx.x;
    const int w    = t >> 5;
    const int lane = t & 31;
    const int r    = w * 16 + (lane >> 2);
    const int cl   = (lane & 3) * 2;

    ((float4*)enc_s)[t] = ((const float4*)(g_enc_proj + (size_t)bt * JD))[t];
    for (int i = t; i < JD; i += 256)
        wb_s[i] = Wout[(size_t)i * VO + (VO - 1)];
    __syncthreads();

    const float* pr0 = g_pred_proj + ((size_t)(b * U_ + r)) * JD;
    const float* pr1 = pr0 + 8 * JD;
    uint4* aOut = g_Afrag + (((size_t)bt * NCHUNK) * 8 + w) * 4 * 32 + lane;
    float accR = 0.f, accR8 = 0.f;

    #pragma unroll 2
    for (int c = 0; c < NCHUNK; c++) {
        #pragma unroll
        for (int kh = 0; kh < 4; kh++) {
            const int j = c * 64 + kh * 16 + cl;
            float2 e0 = *(const float2*)&enc_s[j];
            float2 e1 = *(const float2*)&enc_s[j + 8];
            float2 w0 = *(const float2*)&wb_s[j];
            float2 w1 = *(const float2*)&wb_s[j + 8];
            float2 p00 = *(const float2*)&pr0[j];
            float2 p01 = *(const float2*)&pr0[j + 8];
            float2 p10 = *(const float2*)&pr1[j];
            float2 p11 = *(const float2*)&pr1[j + 8];
            float h00x = fmaxf(p00.x + e0.x, 0.f), h00y = fmaxf(p00.y + e0.y, 0.f);
            float h01x = fmaxf(p01.x + e1.x, 0.f), h01y = fmaxf(p01.y + e1.y, 0.f);
            float h10x = fmaxf(p10.x + e0.x, 0.f), h10y = fmaxf(p10.y + e0.y, 0.f);
            float h11x = fmaxf(p11.x + e1.x, 0.f), h11y = fmaxf(p11.y + e1.y, 0.f);
            accR  += h00x * w0.x + h00y * w0.y + h01x * w1.x + h01y * w1.y;
            accR8 += h10x * w0.x + h10y * w0.y + h11x * w1.x + h11y * w1.y;
            __half2 a0 = __floats2half2_rn(h00x, h00y);
            __half2 a1 = __floats2half2_rn(h10x, h10y);
            __half2 a2 = __floats2half2_rn(h01x, h01y);
            __half2 a3 = __floats2half2_rn(h11x, h11y);
            aOut[(size_t)(c * 8) * 4 * 32 + kh * 32] = make_uint4(
                *(uint32_t*)&a0, *(uint32_t*)&a1, *(uint32_t*)&a2, *(uint32_t*)&a3);
        }
    }

    accR  += __shfl_xor_sync(0xffffffffu, accR, 1);
    accR  += __shfl_xor_sync(0xffffffffu, accR, 2);
    accR8 += __shfl_xor_sync(0xffffffffu, accR8, 1);
    accR8 += __shfl_xor_sync(0xffffffffu, accR8, 2);
    if ((lane & 3) == 0) {
        const float bb = bout[VO - 1];
        out[((size_t)bt * U_ + r) * VO + (VO - 1)]     = accR  + bb;
        out[((size_t)bt * U_ + r + 8) * VO + (VO - 1)] = accR8 + bb;
    }
}

// =====================================================================
// kernel 4: joint GEMM — direct-LDG fragments + L2 prefetch (dist 1)
// CTA 128x128 (bt x n-tile), warps 2(M)x4(N), warp tile 64x32
// =====================================================================
__global__ void __launch_bounds__(256, 2) joint_main(
    const float* __restrict__ bout, float* __restrict__ out)
{
    extern __shared__ char sm[];

    const int bt    = blockIdx.y;          // 0..1023
    const int ntile = blockIdx.x;          // 0..7
    const int n0    = ntile * 128;
    const int t     = threadIdx.x;
    const int warp  = t >> 5;
    const int lane  = t & 31;
    const int wm    = warp >> 2;           // 0..1 (M)
    const int wn    = warp & 3;            // 0..3 (N)

    float acc[4][4][4] = {};

    const uint4* aC = g_Afrag + (((size_t)bt * NCHUNK * 8) + wm * 4) * 128 + lane;
    const uint2* bC = g_Wfrag + (size_t)(ntile * 16 + wn * 4) * 128 + lane;
    // per-CTA chunk region for prefetch (16KB contiguous per chunk)
    const char* aPF = (const char*)(g_Afrag + (size_t)bt * NCHUNK * 1024) + (t & 127) * 128;

    for (int c = 0; c < NCHUNK; c++) {
        if (c + 1 < NCHUNK && t < 128)
            asm volatile("prefetch.global.L2 [%0];"
                         :: "l"(aPF + (size_t)(c + 1) * 16384));
        #pragma unroll
        for (int kh = 0; kh < 4; kh++) {
            uint2 bq[4];
            #pragma unroll
            for (int nt = 0; nt < 4; nt++)
                bq[nt] = bC[(size_t)c * 16384 + nt * 128 + kh * 32];
            #pragma unroll
            for (int mt = 0; mt < 4; mt++) {
                uint4 av = aC[(size_t)c * 1024 + mt * 128 + kh * 32];
                uint32_t a[4] = {av.x, av.y, av.z, av.w};
                #pragma unroll
                for (int nt = 0; nt < 4; nt++)
                    mma16816(acc[mt][nt], a, (const uint32_t*)&bq[nt]);
            }
        }
    }

    // ---- coalesced epilogue: stage f32 tile in smem, then contiguous STG ----
    float* stg = (float*)sm;               // 128 x 132 floats = 67584 B
    const int gid = lane >> 2, tig = lane & 3;
    #pragma unroll
    for (int mt = 0; mt < 4; mt++) {
        #pragma unroll
        for (int nt = 0; nt < 4; nt++) {
            float* cv = acc[mt][nt];
            int u0 = wm * 64 + mt * 16 + gid;
            int c0 = wn * 32 + nt * 8 + tig * 2;
            *(float2*)&stg[u0 * 132 + c0]       = make_float2(cv[0], cv[1]);
            *(float2*)&stg[(u0 + 8) * 132 + c0] = make_float2(cv[2], cv[3]);
        }
    }
    __syncthreads();

    float bo[4];
    #pragma unroll
    for (int i = 0; i < 4; i++) bo[i] = bout[n0 + i * 32 + lane];

    #pragma unroll
    for (int ri = 0; ri < 16; ri++) {
        int row = warp * 16 + ri;
        float* orow = out + ((size_t)bt * U_ + row) * VO + n0;
        #pragma unroll
        for (int i = 0; i < 4; i++)
            orow[i * 32 + lane] = stg[row * 132 + i * 32 + lane] + bo[i];
    }
}

// =====================================================================
extern "C" void kernel_launch(void* const* d_in, const int* in_sizes, int n_in,
                              void* d_out, int out_size)
{
    (void)in_sizes; (void)n_in; (void)out_size;
    const float* enc    = (const float*)d_in[0];
    const float* pred   = (const float*)d_in[1];
    const float* W_enc  = (const float*)d_in[2];
    const float* b_enc  = (const float*)d_in[3];
    const float* W_pred = (const float*)d_in[4];
    const float* b_pred = (const float*)d_in[5];
    const float* W_out  = (const float*)d_in[6];
    const float* b_out  = (const float*)d_in[7];
    float* out = (float*)d_out;

    void *pe, *pp;
    cudaGetSymbolAddress(&pe, g_enc_proj);
    cudaGetSymbolAddress(&pp, g_pred_proj);
    float* genc  = (float*)pe;
    float* gpred = (float*)pp;

    cudaFuncSetAttribute(joint_main, cudaFuncAttributeMaxDynamicSharedMemorySize, SM_TOTAL);

    dim3 pg(JD / 64, (B_ * T_) / 64, 2);     // z=0 enc, z=1 pred (y-guard)
    proj_both<<<pg, 256>>>(enc, W_enc, b_enc, genc,
                           pred, W_pred, b_pred, gpred);
    prep_w<<<1024, 256>>>(W_out);
    precompute_A<<<B_ * T_, 256>>>(W_out, b_out, out);

    dim3 grid(8, B_ * T_);               // 8 n-tiles x 1024 (b,t) tiles
    joint_main<<<grid, 256, SM_TOTAL>>>(b_out, out);
}

// round 15
// speedup vs baseline: 1.1877x; 1.0283x over previous
#include <cuda_runtime.h>
#include <cuda_fp16.h>
#include <stdint.h>

#define B_   4
#define T_   256
#define U_   128
#define DE   512
#define DP   640
#define JD   1024
#define VO   1025

#define KC     64
#define NCHUNK 16

// ---- dynamic smem (joint): epilogue staging only ----
#define SM_TOTAL (128*132*4)             // 67584 -> 2 CTAs/SM

// ---- device scratch ----
__device__ __align__(16) float g_enc_proj[B_*T_*JD];      // 4 MB
__device__ __align__(16) float g_pred_proj[B_*U_*JD];     // 2 MB
// W fragments: uint2 [c(16)][n8(128)][kh(4)][lane(32)]   // 2 MB
__device__ __align__(16) uint2 g_Wfrag[NCHUNK*128*4*32];
// A fragments: uint4 [bt(1024)][c(16)][mh(8)][kh(4)][lane(32)]  // 256 MB
__device__ __align__(16) uint4 g_Afrag[(size_t)B_*T_*NCHUNK*8*4*32];

// =====================================================================
// helpers
// =====================================================================
__device__ __forceinline__ void mma16816(float* c, const uint32_t* a, const uint32_t* b) {
    asm volatile(
        "mma.sync.aligned.m16n8k16.row.col.f32.f16.f16.f32 "
        "{%0,%1,%2,%3},{%4,%5,%6,%7},{%8,%9},{%0,%1,%2,%3};"
        : "+f"(c[0]), "+f"(c[1]), "+f"(c[2]), "+f"(c[3])
        : "r"(a[0]), "r"(a[1]), "r"(a[2]), "r"(a[3]), "r"(b[0]), "r"(b[1]));
}

// =====================================================================
// kernel 1: BOTH fp32 projection GEMMs in one launch (z selects problem)
// =====================================================================
__global__ void __launch_bounds__(256) proj_both(
    const float* __restrict__ A0, const float* __restrict__ W0,
    const float* __restrict__ bias0, float* __restrict__ C0,
    const float* __restrict__ A1, const float* __restrict__ W1,
    const float* __restrict__ bias1, float* __restrict__ C1)
{
    const int which = blockIdx.z;
    const float* A    = which ? A1 : A0;
    const float* W    = which ? W1 : W0;
    const float* bias = which ? bias1 : bias0;
    float* C          = which ? C1 : C0;
    const int M = which ? (B_ * U_) : (B_ * T_);
    const int K = which ? DP : DE;
    const int J = JD;

    const int m0 = blockIdx.y * 64;
    if (m0 >= M) return;
    const int n0 = blockIdx.x * 64;

    __shared__ float As[16][68];
    __shared__ float Bs[16][64];
    const int tx = threadIdx.x & 15;
    const int ty = threadIdx.x >> 4;

    float acc[4][4] = {};

    for (int k0 = 0; k0 < K; k0 += 16) {
        {
            int t = threadIdx.x;
            int m  = t >> 2, k4 = (t & 3) * 4;
            float4 a = *(const float4*)(A + (size_t)(m0 + m) * K + k0 + k4);
            As[k4 + 0][m] = a.x; As[k4 + 1][m] = a.y;
            As[k4 + 2][m] = a.z; As[k4 + 3][m] = a.w;
            int kk = t >> 4, n4 = (t & 15) * 4;
            *(float4*)&Bs[kk][n4] = *(const float4*)(W + (size_t)(k0 + kk) * J + n0 + n4);
        }
        __syncthreads();
        #pragma unroll
        for (int k = 0; k < 16; k++) {
            float a[4], b[4];
            *(float4*)a = *(float4*)&As[k][ty * 4];
            *(float4*)b = *(float4*)&Bs[k][tx * 4];
            #pragma unroll
            for (int i = 0; i < 4; i++)
                #pragma unroll
                for (int j = 0; j < 4; j++)
                    acc[i][j] += a[i] * b[j];
        }
        __syncthreads();
    }
    #pragma unroll
    for (int i = 0; i < 4; i++) {
        int m = m0 + ty * 4 + i;
        #pragma unroll
        for (int j = 0; j < 4; j++) {
            int n = n0 + tx * 4 + j;
            C[(size_t)m * J + n] = acc[i][j] + bias[n];
        }
    }
}

// =====================================================================
// kernel 2: W_out[:, 0:1024] -> fp16 B-fragments (col-major n8k16)
// =====================================================================
__global__ void __launch_bounds__(256) prep_w(const float* __restrict__ W) {
    int idx = blockIdx.x * 256 + threadIdx.x;     // 0..262143
    int lane = idx & 31;
    int kh   = (idx >> 5) & 3;
    int n8   = (idx >> 7) & 127;
    int c    = idx >> 14;
    int j = c * 64 + kh * 16 + (lane & 3) * 2;
    int n = n8 * 8 + (lane >> 2);
    __half2 b0 = __floats2half2_rn(W[(size_t)j * VO + n], W[(size_t)(j + 1) * VO + n]);
    __half2 b1 = __floats2half2_rn(W[(size_t)(j + 8) * VO + n], W[(size_t)(j + 9) * VO + n]);
    g_Wfrag[idx] = make_uint2(*(uint32_t*)&b0, *(uint32_t*)&b1);
}

// =====================================================================
// kernel 3: precompute A-fragments + blank column
// v3: quad-cooperative float4 pred loads + shfl_xor(1) pair exchange.
// Lane q in quad loads cols [(q&1)*8 + (q>>1)*4 .. +4) of its row; the
// parity-selected publish + shfl_xor(1) hands each lane (cl,cl+1,cl+8,cl+9).
// =====================================================================
__global__ void __launch_bounds__(256) precompute_A(
    const float* __restrict__ Wout, const float* __restrict__ bout,
    float* __restrict__ out)
{
    __shared__ float enc_s[JD];
    __shared__ float wb_s[JD];
    const int bt   = blockIdx.x;
    const int b    = bt >> 8;
    const int t    = threadIdx.x;
    const int w    = t >> 5;
    const int lane = t & 31;
    const int q    = lane & 3;
    const int r    = w * 16 + (lane >> 2);
    const int cl   = q * 2;
    const int col0 = (q & 1) * 8 + (q >> 1) * 4;
    const bool odd = (q & 1) != 0;

    ((float4*)enc_s)[t] = ((const float4*)(g_enc_proj + (size_t)bt * JD))[t];
    for (int i = t; i < JD; i += 256)
        wb_s[i] = Wout[(size_t)i * VO + (VO - 1)];
    __syncthreads();

    const float* pr0 = g_pred_proj + ((size_t)(b * U_ + r)) * JD;
    const float* pr1 = pr0 + 8 * JD;
    uint4* aOut = g_Afrag + (((size_t)bt * NCHUNK) * 8 + w) * 4 * 32 + lane;
    float accR = 0.f, accR8 = 0.f;

    #pragma unroll 2
    for (int c = 0; c < NCHUNK; c++) {
        #pragma unroll
        for (int kh = 0; kh < 4; kh++) {
            const int j0 = c * 64 + kh * 16;
            float4 f0 = *(const float4*)(pr0 + j0 + col0);
            float4 f1 = *(const float4*)(pr1 + j0 + col0);

            // pair exchange within parity pair (lanes 2k <-> 2k+1)
            float p0x = odd ? f0.x : f0.z, p0y = odd ? f0.y : f0.w;
            float p1x = odd ? f1.x : f1.z, p1y = odd ? f1.y : f1.w;
            float g0x = __shfl_xor_sync(0xffffffffu, p0x, 1);
            float g0y = __shfl_xor_sync(0xffffffffu, p0y, 1);
            float g1x = __shfl_xor_sync(0xffffffffu, p1x, 1);
            float g1y = __shfl_xor_sync(0xffffffffu, p1y, 1);

            // row r: lo = cols (cl, cl+1), hi = cols (cl+8, cl+9)
            float lo0x = odd ? g0x : f0.x, lo0y = odd ? g0y : f0.y;
            float hi0x = odd ? f0.z : g0x, hi0y = odd ? f0.w : g0y;
            // row r+8
            float lo1x = odd ? g1x : f1.x, lo1y = odd ? g1y : f1.y;
            float hi1x = odd ? f1.z : g1x, hi1y = odd ? f1.w : g1y;

            float2 e0 = *(const float2*)&enc_s[j0 + cl];
            float2 e1 = *(const float2*)&enc_s[j0 + cl + 8];
            float2 w0 = *(const float2*)&wb_s[j0 + cl];
            float2 w1 = *(const float2*)&wb_s[j0 + cl + 8];

            float h00x = fmaxf(lo0x + e0.x, 0.f), h00y = fmaxf(lo0y + e0.y, 0.f);
            float h01x = fmaxf(hi0x + e1.x, 0.f), h01y = fmaxf(hi0y + e1.y, 0.f);
            float h10x = fmaxf(lo1x + e0.x, 0.f), h10y = fmaxf(lo1y + e0.y, 0.f);
            float h11x = fmaxf(hi1x + e1.x, 0.f), h11y = fmaxf(hi1y + e1.y, 0.f);

            accR  += h00x * w0.x + h00y * w0.y + h01x * w1.x + h01y * w1.y;
            accR8 += h10x * w0.x + h10y * w0.y + h11x * w1.x + h11y * w1.y;

            __half2 a0 = __floats2half2_rn(h00x, h00y);
            __half2 a1 = __floats2half2_rn(h10x, h10y);
            __half2 a2 = __floats2half2_rn(h01x, h01y);
            __half2 a3 = __floats2half2_rn(h11x, h11y);
            aOut[(size_t)(c * 8) * 4 * 32 + kh * 32] = make_uint4(
                *(uint32_t*)&a0, *(uint32_t*)&a1, *(uint32_t*)&a2, *(uint32_t*)&a3);
        }
    }

    accR  += __shfl_xor_sync(0xffffffffu, accR, 1);
    accR  += __shfl_xor_sync(0xffffffffu, accR, 2);
    accR8 += __shfl_xor_sync(0xffffffffu, accR8, 1);
    accR8 += __shfl_xor_sync(0xffffffffu, accR8, 2);
    if (q == 0) {
        const float bb = bout[VO - 1];
        out[((size_t)bt * U_ + r) * VO + (VO - 1)]     = accR  + bb;
        out[((size_t)bt * U_ + r + 8) * VO + (VO - 1)] = accR8 + bb;
    }
}

// =====================================================================
// kernel 4: joint GEMM — direct-LDG fragments + L2 prefetch (dist 1)
// (round-14 proven version, untouched)
// =====================================================================
__global__ void __launch_bounds__(256, 2) joint_main(
    const float* __restrict__ bout, float* __restrict__ out)
{
    extern __shared__ char sm[];

    const int bt    = blockIdx.y;          // 0..1023
    const int ntile = blockIdx.x;          // 0..7
    const int n0    = ntile * 128;
    const int t     = threadIdx.x;
    const int warp  = t >> 5;
    const int lane  = t & 31;
    const int wm    = warp >> 2;           // 0..1 (M)
    const int wn    = warp & 3;            // 0..3 (N)

    float acc[4][4][4] = {};

    const uint4* aC = g_Afrag + (((size_t)bt * NCHUNK * 8) + wm * 4) * 128 + lane;
    const uint2* bC = g_Wfrag + (size_t)(ntile * 16 + wn * 4) * 128 + lane;
    const char* aPF = (const char*)(g_Afrag + (size_t)bt * NCHUNK * 1024) + (t & 127) * 128;

    for (int c = 0; c < NCHUNK; c++) {
        if (c + 1 < NCHUNK && t < 128)
            asm volatile("prefetch.global.L2 [%0];"
                         :: "l"(aPF + (size_t)(c + 1) * 16384));
        #pragma unroll
        for (int kh = 0; kh < 4; kh++) {
            uint2 bq[4];
            #pragma unroll
            for (int nt = 0; nt < 4; nt++)
                bq[nt] = bC[(size_t)c * 16384 + nt * 128 + kh * 32];
            #pragma unroll
            for (int mt = 0; mt < 4; mt++) {
                uint4 av = aC[(size_t)c * 1024 + mt * 128 + kh * 32];
                uint32_t a[4] = {av.x, av.y, av.z, av.w};
                #pragma unroll
                for (int nt = 0; nt < 4; nt++)
                    mma16816(acc[mt][nt], a, (const uint32_t*)&bq[nt]);
            }
        }
    }

    // ---- coalesced epilogue: stage f32 tile in smem, then contiguous STG ----
    float* stg = (float*)sm;               // 128 x 132 floats = 67584 B
    const int gid = lane >> 2, tig = lane & 3;
    #pragma unroll
    for (int mt = 0; mt < 4; mt++) {
        #pragma unroll
        for (int nt = 0; nt < 4; nt++) {
            float* cv = acc[mt][nt];
            int u0 = wm * 64 + mt * 16 + gid;
            int c0 = wn * 32 + nt * 8 + tig * 2;
            *(float2*)&stg[u0 * 132 + c0]       = make_float2(cv[0], cv[1]);
            *(float2*)&stg[(u0 + 8) * 132 + c0] = make_float2(cv[2], cv[3]);
        }
    }
    __syncthreads();

    float bo[4];
    #pragma unroll
    for (int i = 0; i < 4; i++) bo[i] = bout[n0 + i * 32 + lane];

    #pragma unroll
    for (int ri = 0; ri < 16; ri++) {
        int row = warp * 16 + ri;
        float* orow = out + ((size_t)bt * U_ + row) * VO + n0;
        #pragma unroll
        for (int i = 0; i < 4; i++)
            orow[i * 32 + lane] = stg[row * 132 + i * 32 + lane] + bo[i];
    }
}

// =====================================================================
extern "C" void kernel_launch(void* const* d_in, const int* in_sizes, int n_in,
                              void* d_out, int out_size)
{
    (void)in_sizes; (void)n_in; (void)out_size;
    const float* enc    = (const float*)d_in[0];
    const float* pred   = (const float*)d_in[1];
    const float* W_enc  = (const float*)d_in[2];
    const float* b_enc  = (const float*)d_in[3];
    const float* W_pred = (const float*)d_in[4];
    const float* b_pred = (const float*)d_in[5];
    const float* W_out  = (const float*)d_in[6];
    const float* b_out  = (const float*)d_in[7];
    float* out = (float*)d_out;

    void *pe, *pp;
    cudaGetSymbolAddress(&pe, g_enc_proj);
    cudaGetSymbolAddress(&pp, g_pred_proj);
    float* genc  = (float*)pe;
    float* gpred = (float*)pp;

    cudaFuncSetAttribute(joint_main, cudaFuncAttributeMaxDynamicSharedMemorySize, SM_TOTAL);

    dim3 pg(JD / 64, (B_ * T_) / 64, 2);     // z=0 enc, z=1 pred (y-guard)
    proj_both<<<pg, 256>>>(enc, W_enc, b_enc, genc,
                           pred, W_pred, b_pred, gpred);
    prep_w<<<1024, 256>>>(W_out);
    precompute_A<<<B_ * T_, 256>>>(W_out, b_out, out);

    dim3 grid(8, B_ * T_);               // 8 n-tiles x 1024 (b,t) tiles
    joint_main<<<grid, 256, SM_TOTAL>>>(b_out, out);
}